// round 9
// baseline (speedup 1.0000x reference)
#include <cuda_runtime.h>
#include <math.h>
#include <stdint.h>

#define NX    2000
#define NZ    4
#define TT    16
#define KDIM  24000   // 3*2000*4
#define NOUT  8000    // nz*nx
#define NCOL  64      // TT*NZ

#define KSPLIT 9
#define KT     32
#define NTILES (KDIM / KT)        // 750
#define TPK    84                 // ceil(750/9)

__device__ float  g_zg[NX * NCOL];                // (2000, 64)
__device__ float2 g_zpair[8 * KDIM];              // [tp][k] = (z[2tp][k], z[2tp+1][k])
__device__ float  g_scratch[KSPLIT * NOUT * TT];  // [kb][n][t]

union F2U { float2 f; unsigned long long u; };
__device__ __forceinline__ void ffma2(F2U& d, const F2U a, const F2U b) {
    asm("fma.rn.f32x2 %0, %1, %2, %0;" : "+l"(d.u) : "l"(a.u), "l"(b.u));
}
__device__ __forceinline__ uint32_t s2u(const void* p) {
    uint32_t a;
    asm("{ .reg .u64 t; cvta.to.shared.u64 t, %1; cvt.u32.u64 %0, t; }" : "=r"(a) : "l"(p));
    return a;
}
__device__ __forceinline__ void bulk_g2s(uint32_t dst, const void* src, int bytes, uint32_t mbar) {
    asm volatile("cp.async.bulk.shared::cta.global.mbarrier::complete_tx::bytes [%0], [%1], %2, [%3];"
                 :: "r"(dst), "l"(src), "r"(bytes), "r"(mbar) : "memory");
}
__device__ __forceinline__ void mbar_init(uint32_t mbar, int cnt) {
    asm volatile("mbarrier.init.shared.b64 [%0], %1;" :: "r"(mbar), "r"(cnt) : "memory");
}
__device__ __forceinline__ void mbar_expect(uint32_t mbar, int bytes) {
    asm volatile("mbarrier.arrive.expect_tx.shared.b64 _, [%0], %1;" :: "r"(mbar), "r"(bytes) : "memory");
}
__device__ __forceinline__ void mbar_wait(uint32_t mbar, int phase) {
    asm volatile("{\n\t.reg .pred P;\n\t"
                 "WL_%=:\n\t"
                 "mbarrier.try_wait.parity.acquire.cta.shared::cta.b64 P, [%0], %1, 0x989680;\n\t"
                 "@P bra.uni WD_%=;\n\t"
                 "bra.uni WL_%=;\n\t"
                 "WD_%=:\n\t}"
                 :: "r"(mbar), "r"(phase) : "memory");
}

// ---------- kernel 1: gather g_zg ----------
__global__ void gather_kernel(const float* __restrict__ factors,
                              const int*   __restrict__ t_idx) {
    int gid = blockIdx.x * blockDim.x + threadIdx.x;
    if (gid < NX * NCOL) {
        int y = gid >> 6, n = gid & 63;
        int t = n >> 2, zi = n & 3;
        g_zg[gid] = factors[(long)t_idx[t] * NOUT + y * NZ + zi];
    }
}

// ---------- kernel 2: relation GEMM (4000x2000)@(2000x64), scatter into zpair ----------
#define KT1 100
__global__ __launch_bounds__(256) void gemm1_kernel(const float* __restrict__ rel) {
    __shared__ float rel_sT[KT1][36];
    __shared__ float zg_s[KT1][64];
    int tid = threadIdx.x;
    int mg = tid >> 5, ng = tid & 31;      // 8 m-groups x 32 n-groups
    int mbase = blockIdx.x * 32;

    F2U acc[2][2];
    acc[0][0].f = acc[0][1].f = acc[1][0].f = acc[1][1].f = make_float2(0.f, 0.f);

    for (int kt = 0; kt < NX; kt += KT1) {
        for (int i = tid; i < 800; i += 256) {           // 32 m x 25 q
            int m = i & 31, q = i >> 5;
            float4 v = *(const float4*)&rel[(long)(mbase + m) * NX + kt + q * 4];
            rel_sT[q*4+0][m] = v.x; rel_sT[q*4+1][m] = v.y;
            rel_sT[q*4+2][m] = v.z; rel_sT[q*4+3][m] = v.w;
        }
        for (int i = tid; i < KT1 * 64 / 4; i += 256)
            ((float4*)zg_s)[i] = ((const float4*)(g_zg + kt * 64))[i];
        __syncthreads();

        #pragma unroll 4
        for (int k = 0; k < KT1; k++) {
            float4 a4 = *(float4*)&rel_sT[k][mg * 4];
            float2 b2 = *(float2*)&zg_s[k][ng * 2];
            F2U a2[2];
            a2[0].f = make_float2(a4.x, a4.y);
            a2[1].f = make_float2(a4.z, a4.w);
            F2U b0; b0.f = make_float2(b2.x, b2.x);
            F2U b1; b1.f = make_float2(b2.y, b2.y);
            ffma2(acc[0][0], a2[0], b0);
            ffma2(acc[1][0], a2[1], b0);
            ffma2(acc[0][1], a2[0], b1);
            ffma2(acc[1][1], a2[1], b1);
        }
        __syncthreads();
    }
    // scatter: m0 even -> r=1 (.x), m0+1 odd -> r=2 (.y); col n = ng*2+j
    float* zp = (float*)g_zpair;
    #pragma unroll
    for (int mp = 0; mp < 2; mp++)
        #pragma unroll
        for (int j = 0; j < 2; j++) {
            int m0 = mbase + mg * 4 + mp * 2;
            int x  = m0 >> 1;
            int n  = ng * 2 + j;
            int t  = n >> 2, z = n & 3;
            int tp = t >> 1, half = t & 1;
            float2 v = acc[mp][j].f;
            zp[((size_t)tp * KDIM +  8000 + x * 4 + z) * 2 + half] = v.x;
            zp[((size_t)tp * KDIM + 16000 + x * 4 + z) * 2 + half] = v.y;
        }
}

// ---------- kernel 2.5: pack identity region (k < 8000) from factors ----------
__global__ void pack_kernel(const float* __restrict__ factors,
                            const int*   __restrict__ t_idx) {
    int gid = blockIdx.x * blockDim.x + threadIdx.x;
    if (gid >= 8 * NOUT) return;
    int tp = gid / NOUT, k = gid - tp * NOUT;
    int i0 = t_idx[2 * tp], i1 = t_idx[2 * tp + 1];
    g_zpair[(size_t)tp * KDIM + k] =
        make_float2(factors[(size_t)i0 * NOUT + k], factors[(size_t)i1 * NOUT + k]);
}

// ---------- kernel 3: MLP partial GEMM — bulk-copy double-buffered ----------
// block: 128 threads, 256 W-rows x 16 t. thread = 4 rows x 4 t-pairs.
// smem: W [2][256][36] (73728 B) + Z [2][8][68] (4352 B) + mbar -> 78112 B, 2 blocks/SM
#define WSTRIDE 36
#define ZSTRIDE 68
#define WBUFF   (256 * WSTRIDE)          // floats
#define ZBASE   (2 * WBUFF)
#define ZBUFF   (8 * ZSTRIDE)
#define MBAR_OFF ((ZBASE + 2 * ZBUFF) * 4)
#define SMEM_BYTES (MBAR_OFF + 32)
#define TILE_BYTES (256 * 128 + 8 * 256) // 34816

__global__ __launch_bounds__(128, 2) void mlp_kernel(const float* __restrict__ W) {
    extern __shared__ float sm[];
    uint32_t sb = s2u(sm);
    int tid = threadIdx.x, lane = tid & 31, warp = tid >> 5;
    int rowblk = blockIdx.x, kb = blockIdx.y;

    int row0 = rowblk * 256;
    if (row0 > NOUT - 256) row0 = NOUT - 256;     // benign duplicate rows
    int t0 = kb * TPK;
    int t1 = t0 + TPK; if (t1 > NTILES) t1 = NTILES;
    int nt = t1 - t0;

    int rg  = lane >> 1;            // 0..15
    int tpg = lane & 1;             // 0..1
    int tp0 = tpg * 4;              // 4 t-pairs per thread
    int r_loc = warp * 64 + rg;     // rows r_loc + 16*i, i=0..3

    uint32_t mb = sb + MBAR_OFF;
    if (tid == 0) { mbar_init(mb, 1); mbar_init(mb + 8, 1); }
    __syncthreads();
    int ph0 = 0, ph1 = 0;

    F2U acc[4][4];
    #pragma unroll
    for (int i = 0; i < 4; i++)
        #pragma unroll
        for (int j = 0; j < 4; j++) acc[i][j].f = make_float2(0.f, 0.f);

    const float2* zp = g_zpair;

    auto bulk_load = [&](int tile, int buf) {
        int k0 = (t0 + tile) * KT;
        // W: 256 rows, two per thread (tid, tid+128)
        uint32_t mbar = mb + buf * 8;
        bulk_g2s(sb + (buf * WBUFF + tid * WSTRIDE) * 4,
                 W + (size_t)(row0 + tid) * KDIM + k0, 128, mbar);
        bulk_g2s(sb + (buf * WBUFF + (tid + 128) * WSTRIDE) * 4,
                 W + (size_t)(row0 + tid + 128) * KDIM + k0, 128, mbar);
        if (tid < 8)
            bulk_g2s(sb + (ZBASE + buf * ZBUFF + tid * ZSTRIDE) * 4,
                     (const char*)zp + ((size_t)tid * KDIM + k0) * 8, 256, mbar);
    };

    if (tid == 0) mbar_expect(mb, TILE_BYTES);
    __syncthreads();
    bulk_load(0, 0);

    for (int i = 0; i < nt; i++) {
        int buf = i & 1;
        if (i + 1 < nt) {
            if (tid == 0) mbar_expect(mb + (buf ^ 1) * 8, TILE_BYTES);
            __syncthreads();    // orders expect before bulks; buffer freed by all threads
            bulk_load(i + 1, buf ^ 1);
        }
        if (buf) { mbar_wait(mb + 8, ph1); ph1 ^= 1; }
        else     { mbar_wait(mb,     ph0); ph0 ^= 1; }

        const float* Wt = sm + buf * WBUFF;
        const float* Zt = sm + ZBASE + buf * ZBUFF;
        #pragma unroll
        for (int kk = 0; kk < KT; kk += 4) {
            float4 wv[4];
            #pragma unroll
            for (int i2 = 0; i2 < 4; i2++)
                wv[i2] = *(const float4*)&Wt[(r_loc + 16 * i2) * WSTRIDE + kk];
            F2U zf[4][4];
            #pragma unroll
            for (int j = 0; j < 4; j++) {
                float4 a = *(const float4*)&Zt[(tp0 + j) * ZSTRIDE + kk * 2];
                float4 b = *(const float4*)&Zt[(tp0 + j) * ZSTRIDE + kk * 2 + 4];
                zf[j][0].f = make_float2(a.x, a.y);
                zf[j][1].f = make_float2(a.z, a.w);
                zf[j][2].f = make_float2(b.x, b.y);
                zf[j][3].f = make_float2(b.z, b.w);
            }
            #pragma unroll
            for (int i2 = 0; i2 < 4; i2++) {
                float ws[4] = {wv[i2].x, wv[i2].y, wv[i2].z, wv[i2].w};
                #pragma unroll
                for (int q = 0; q < 4; q++) {
                    F2U w2; w2.f = make_float2(ws[q], ws[q]);
                    #pragma unroll
                    for (int j = 0; j < 4; j++)
                        ffma2(acc[i2][j], w2, zf[j][q]);
                }
            }
        }
    }

    float2* sc = (float2*)g_scratch;
    #pragma unroll
    for (int i2 = 0; i2 < 4; i2++) {
        int row = row0 + r_loc + 16 * i2;
        #pragma unroll
        for (int j = 0; j < 4; j++)
            sc[((size_t)kb * NOUT + row) * 8 + tp0 + j] = acc[i2][j].f;
    }
}

// ---------- kernel 4: epilogue — sum partials + bias + tanh ----------
__global__ void epilogue_kernel(const float* __restrict__ bias,
                                float* __restrict__ out) {
    int idx = blockIdx.x * blockDim.x + threadIdx.x;
    if (idx >= NOUT * 4) return;
    int n = idx >> 2, tq = idx & 3;
    float4 s = make_float4(0.f, 0.f, 0.f, 0.f);
    #pragma unroll
    for (int kb = 0; kb < KSPLIT; kb++) {
        float4 v = *(const float4*)&g_scratch[((size_t)kb * NOUT + n) * TT + tq * 4];
        s.x += v.x; s.y += v.y; s.z += v.z; s.w += v.w;
    }
    float b = bias[n];
    out[(size_t)(tq*4+0) * NOUT + n] = tanhf(s.x + b);
    out[(size_t)(tq*4+1) * NOUT + n] = tanhf(s.y + b);
    out[(size_t)(tq*4+2) * NOUT + n] = tanhf(s.z + b);
    out[(size_t)(tq*4+3) * NOUT + n] = tanhf(s.w + b);
}

extern "C" void kernel_launch(void* const* d_in, const int* in_sizes, int n_in,
                              void* d_out, int out_size) {
    const float* relations = (const float*)d_in[0];
    const float* factors   = (const float*)d_in[1];
    const float* W_dyn     = (const float*)d_in[2];
    const float* b_dyn     = (const float*)d_in[3];
    const int*   t_idx     = (const int*)d_in[4];
    float* out = (float*)d_out;

    cudaFuncSetAttribute(mlp_kernel, cudaFuncAttributeMaxDynamicSharedMemorySize, SMEM_BYTES);

    gather_kernel<<<(NX * NCOL + 255) / 256, 256>>>(factors, t_idx);
    gemm1_kernel<<<125, 256>>>(relations);
    pack_kernel<<<(8 * NOUT + 255) / 256, 256>>>(factors, t_idx);
    dim3 grid(32, KSPLIT);      // 32 row-blocks x 9 k-splits = 288 blocks
    mlp_kernel<<<grid, 128, SMEM_BYTES>>>(W_dyn);
    epilogue_kernel<<<(NOUT * 4 + 255) / 256, 256>>>(b_dyn, out);
}

// round 10
// speedup vs baseline: 1.0030x; 1.0030x over previous
#include <cuda_runtime.h>
#include <math.h>
#include <stdint.h>

#define NX    2000
#define NZ    4
#define TT    16
#define KDIM  24000   // 3*2000*4
#define NOUT  8000    // nz*nx
#define NCOL  64      // TT*NZ

#define KSPLIT 9
#define KT     32
#define NTILES (KDIM / KT)        // 750
#define TPK    84                 // ceil(750/9)

__device__ float g_zctx[TT * KDIM];              // (16, 24000) row-major
__device__ float g_zgT[NCOL * NX];               // [n][y], n = t*4+z
__device__ float g_scratch[KSPLIT * NOUT * TT];  // [kb][n][t]

typedef unsigned long long ull;
union F2U { float2 f; ull u; };
__device__ __forceinline__ void ffma2u(ull& d, ull a, ull b) {
    asm("fma.rn.f32x2 %0, %1, %2, %0;" : "+l"(d) : "l"(a), "l"(b));
}
__device__ __forceinline__ uint32_t s2u(const void* p) {
    uint32_t a;
    asm("{ .reg .u64 t; cvta.to.shared.u64 t, %1; cvt.u32.u64 %0, t; }" : "=r"(a) : "l"(p));
    return a;
}
__device__ __forceinline__ void bulk_g2s(uint32_t dst, const void* src, int bytes, uint32_t mbar) {
    asm volatile("cp.async.bulk.shared::cta.global.mbarrier::complete_tx::bytes [%0], [%1], %2, [%3];"
                 :: "r"(dst), "l"(src), "r"(bytes), "r"(mbar) : "memory");
}
__device__ __forceinline__ void mbar_init(uint32_t mbar, int cnt) {
    asm volatile("mbarrier.init.shared.b64 [%0], %1;" :: "r"(mbar), "r"(cnt) : "memory");
}
__device__ __forceinline__ void mbar_expect(uint32_t mbar, int bytes) {
    asm volatile("mbarrier.arrive.expect_tx.shared.b64 _, [%0], %1;" :: "r"(mbar), "r"(bytes) : "memory");
}
__device__ __forceinline__ void mbar_wait(uint32_t mbar, int phase) {
    asm volatile("{\n\t.reg .pred P;\n\t"
                 "WL_%=:\n\t"
                 "mbarrier.try_wait.parity.acquire.cta.shared::cta.b64 P, [%0], %1, 0x989680;\n\t"
                 "@P bra.uni WD_%=;\n\t"
                 "bra.uni WL_%=;\n\t"
                 "WD_%=:\n\t}"
                 :: "r"(mbar), "r"(phase) : "memory");
}

// ---------- kernel 1: gather (zgT transpose + identity block of zctx) ----------
__global__ void gather_kernel(const float* __restrict__ factors,
                              const int*   __restrict__ t_idx) {
    int gid = blockIdx.x * blockDim.x + threadIdx.x;
    if (gid < NCOL * NX) {
        int n = gid / NX, y = gid - n * NX;
        int t = n >> 2, zi = n & 3;
        g_zgT[gid] = factors[(size_t)t_idx[t] * NOUT + y * NZ + zi];
    } else {
        int i = gid - NCOL * NX;
        if (i < TT * NOUT / 4) {
            int t = i / (NOUT / 4);
            int j = i - t * (NOUT / 4);
            ((float4*)g_zctx)[(size_t)t * (KDIM / 4) + j] =
                ((const float4*)factors)[(size_t)t_idx[t] * (NOUT / 4) + j];
        }
    }
}

// ---------- kernel 2: relation GEMM (4000x2000)@(2000x64), k-paired FFMA2 ----------
// block: 16 m-rows x 64 n, 256 threads, thread = 2m x 2n. grid 250.
#define KT1  100
#define PSTR 108    // padded k stride (words), 108%4==0, 12r mod 32 distinct
__global__ __launch_bounds__(256) void gemm1_kernel(const float* __restrict__ rel) {
    __shared__ float a_s[16 * PSTR];
    __shared__ float z_s[64 * PSTR];
    int tid = threadIdx.x;
    int lane = tid & 31, warp = tid >> 5;
    int mlow = (lane >> 2) & 7;          // 0..7
    int nb   = warp * 8 + (lane & 3) * 2;
    int mbase = blockIdx.x * 16;

    ull acc[2][2] = {{0, 0}, {0, 0}};

    for (int kt = 0; kt < NX; kt += KT1) {
        for (int idx = tid; idx < 400; idx += 256) {       // a: 16 x 25 float4
            int row = idx / 25, q = idx - row * 25;
            *(float4*)&a_s[row * PSTR + q * 4] =
                *(const float4*)&rel[(size_t)(mbase + row) * NX + kt + q * 4];
        }
        for (int idx = tid; idx < 1600; idx += 256) {      // z: 64 x 25 float4
            int row = idx / 25, q = idx - row * 25;
            *(float4*)&z_s[row * PSTR + q * 4] =
                *(const float4*)&g_zgT[(size_t)row * NX + kt + q * 4];
        }
        __syncthreads();

        #pragma unroll 5
        for (int kk = 0; kk < KT1; kk += 4) {
            ulonglong2 am[2], zn[2];
            am[0] = *(const ulonglong2*)&a_s[(mlow)     * PSTR + kk];
            am[1] = *(const ulonglong2*)&a_s[(mlow + 8) * PSTR + kk];
            zn[0] = *(const ulonglong2*)&z_s[(nb)       * PSTR + kk];
            zn[1] = *(const ulonglong2*)&z_s[(nb + 1)   * PSTR + kk];
            #pragma unroll
            for (int i = 0; i < 2; i++)
                #pragma unroll
                for (int j = 0; j < 2; j++) {
                    ffma2u(acc[i][j], am[i].x, zn[j].x);
                    ffma2u(acc[i][j], am[i].y, zn[j].y);
                }
        }
        __syncthreads();
    }
    #pragma unroll
    for (int i = 0; i < 2; i++)
        #pragma unroll
        for (int j = 0; j < 2; j++) {
            int m = mbase + mlow + 8 * i;
            int n = nb + j;
            int x = m >> 1, r = (m & 1) + 1;
            int t = n >> 2, zi = n & 3;
            F2U v; v.u = acc[i][j];
            g_zctx[(size_t)t * KDIM + r * NOUT + x * NZ + zi] = v.f.x + v.f.y;
        }
}

// ---------- kernel 3: MLP partial GEMM, k-paired FFMA2, bulk double-buffered ----------
// block: 256 threads, 256 W-rows x 16 t. thread = 4 rows (stride 64) x 4 t (stride 4).
// smem: W [2][256][36] + Z [2][16][36] = 78336 B + mbar -> 2 blocks/SM
#define WSTRIDE 36
#define WBUFF   (256 * WSTRIDE)
#define ZBASE   (2 * WBUFF)
#define ZBUFF   (16 * WSTRIDE)
#define MBAR_OFF ((ZBASE + 2 * ZBUFF) * 4)
#define SMEM_BYTES (MBAR_OFF + 32)
#define TILE_BYTES (256 * 128 + 16 * 128)   // 34816

__global__ __launch_bounds__(256, 2) void mlp_kernel(const float* __restrict__ W) {
    extern __shared__ float sm[];
    uint32_t sb = s2u(sm);
    int tid = threadIdx.x;
    int tg  = tid & 3;            // t low
    int rid = tid >> 2;           // 0..63
    int rowblk = blockIdx.x, kb = blockIdx.y;

    int row0 = rowblk * 256;
    if (row0 > NOUT - 256) row0 = NOUT - 256;     // benign duplicate rows
    int t0 = kb * TPK;
    int t1 = t0 + TPK; if (t1 > NTILES) t1 = NTILES;
    int nt = t1 - t0;

    uint32_t mb = sb + MBAR_OFF;
    if (tid == 0) { mbar_init(mb, 1); mbar_init(mb + 8, 1); }
    __syncthreads();
    int ph0 = 0, ph1 = 0;

    ull acc[4][4];
    #pragma unroll
    for (int i = 0; i < 4; i++)
        #pragma unroll
        for (int j = 0; j < 4; j++) acc[i][j] = 0;

    auto bulk_load = [&](int tile, int buf) {
        int k0 = (t0 + tile) * KT;
        uint32_t mbar = mb + buf * 8;
        bulk_g2s(sb + (buf * WBUFF + tid * WSTRIDE) * 4,
                 W + (size_t)(row0 + tid) * KDIM + k0, 128, mbar);
        if (tid < 16)
            bulk_g2s(sb + (ZBASE + buf * ZBUFF + tid * WSTRIDE) * 4,
                     g_zctx + (size_t)tid * KDIM + k0, 128, mbar);
    };

    if (tid == 0) mbar_expect(mb, TILE_BYTES);
    __syncthreads();
    bulk_load(0, 0);

    for (int it = 0; it < nt; it++) {
        int buf = it & 1;
        if (it + 1 < nt) {
            if (tid == 0) mbar_expect(mb + (buf ^ 1) * 8, TILE_BYTES);
            __syncthreads();
            bulk_load(it + 1, buf ^ 1);
        }
        if (buf) { mbar_wait(mb + 8, ph1); ph1 ^= 1; }
        else     { mbar_wait(mb,     ph0); ph0 ^= 1; }

        const float* Wt = sm + buf * WBUFF;
        const float* Zt = sm + ZBASE + buf * ZBUFF;
        #pragma unroll
        for (int kk = 0; kk < KT; kk += 4) {
            ulonglong2 wv[4], zv[4];
            #pragma unroll
            for (int i = 0; i < 4; i++)
                wv[i] = *(const ulonglong2*)&Wt[(rid + 64 * i) * WSTRIDE + kk];
            #pragma unroll
            for (int j = 0; j < 4; j++)
                zv[j] = *(const ulonglong2*)&Zt[(tg + 4 * j) * WSTRIDE + kk];
            #pragma unroll
            for (int i = 0; i < 4; i++)
                #pragma unroll
                for (int j = 0; j < 4; j++) {
                    ffma2u(acc[i][j], wv[i].x, zv[j].x);
                    ffma2u(acc[i][j], wv[i].y, zv[j].y);
                }
        }
    }

    #pragma unroll
    for (int i = 0; i < 4; i++) {
        int row = row0 + rid + 64 * i;
        #pragma unroll
        for (int j = 0; j < 4; j++) {
            F2U v; v.u = acc[i][j];
            g_scratch[((size_t)kb * NOUT + row) * TT + tg + 4 * j] = v.f.x + v.f.y;
        }
    }
}

// ---------- kernel 4: epilogue — sum partials + bias + tanh ----------
__global__ void epilogue_kernel(const float* __restrict__ bias,
                                float* __restrict__ out) {
    int idx = blockIdx.x * blockDim.x + threadIdx.x;
    if (idx >= NOUT * 4) return;
    int n = idx >> 2, tq = idx & 3;
    float4 s = make_float4(0.f, 0.f, 0.f, 0.f);
    #pragma unroll
    for (int kb = 0; kb < KSPLIT; kb++) {
        float4 v = *(const float4*)&g_scratch[((size_t)kb * NOUT + n) * TT + tq * 4];
        s.x += v.x; s.y += v.y; s.z += v.z; s.w += v.w;
    }
    float b = bias[n];
    out[(size_t)(tq*4+0) * NOUT + n] = tanhf(s.x + b);
    out[(size_t)(tq*4+1) * NOUT + n] = tanhf(s.y + b);
    out[(size_t)(tq*4+2) * NOUT + n] = tanhf(s.z + b);
    out[(size_t)(tq*4+3) * NOUT + n] = tanhf(s.w + b);
}

extern "C" void kernel_launch(void* const* d_in, const int* in_sizes, int n_in,
                              void* d_out, int out_size) {
    const float* relations = (const float*)d_in[0];
    const float* factors   = (const float*)d_in[1];
    const float* W_dyn     = (const float*)d_in[2];
    const float* b_dyn     = (const float*)d_in[3];
    const int*   t_idx     = (const int*)d_in[4];
    float* out = (float*)d_out;

    cudaFuncSetAttribute(mlp_kernel, cudaFuncAttributeMaxDynamicSharedMemorySize, SMEM_BYTES);

    gather_kernel<<<625, 256>>>(factors, t_idx);       // 160000 threads
    gemm1_kernel<<<250, 256>>>(relations);
    dim3 grid(32, KSPLIT);      // 32 row-blocks x 9 k-splits = 288 blocks
    mlp_kernel<<<grid, 256, SMEM_BYTES>>>(W_dyn);
    epilogue_kernel<<<(NOUT * 4 + 255) / 256, 256>>>(b_dyn, out);
}

// round 11
// speedup vs baseline: 1.4037x; 1.3995x over previous
#include <cuda_runtime.h>
#include <cuda.h>
#include <math.h>
#include <stdint.h>

#define NX    2000
#define NZ    4
#define TT    16
#define KDIM  24000   // 3*2000*4
#define NOUT  8000    // nz*nx
#define NCOL  64      // TT*NZ

#define KSPLIT 9
#define KT     32
#define NTILES (KDIM / KT)        // 750
#define TPK    84                 // ceil(750/9)

__device__ float g_zctx[TT * KDIM];              // (16, 24000) row-major
__device__ float g_zgT[NCOL * NX];               // [n][y], n = t*4+z
__device__ float g_scratch[KSPLIT * NOUT * TT];  // [kb][n][t]

typedef unsigned long long ull;
union F2U { float2 f; ull u; };
__device__ __forceinline__ void ffma2u(ull& d, ull a, ull b) {
    asm("fma.rn.f32x2 %0, %1, %2, %0;" : "+l"(d) : "l"(a), "l"(b));
}
__device__ __forceinline__ uint32_t s2u(const void* p) {
    uint32_t a;
    asm("{ .reg .u64 t; cvta.to.shared.u64 t, %1; cvt.u32.u64 %0, t; }" : "=r"(a) : "l"(p));
    return a;
}
__device__ __forceinline__ void mbar_init(uint32_t mbar, int cnt) {
    asm volatile("mbarrier.init.shared.b64 [%0], %1;" :: "r"(mbar), "r"(cnt) : "memory");
}
__device__ __forceinline__ void mbar_expect(uint32_t mbar, int bytes) {
    asm volatile("mbarrier.arrive.expect_tx.shared.b64 _, [%0], %1;" :: "r"(mbar), "r"(bytes) : "memory");
}
__device__ __forceinline__ void mbar_wait(uint32_t mbar, int phase) {
    asm volatile("{\n\t.reg .pred P;\n\t"
                 "WL_%=:\n\t"
                 "mbarrier.try_wait.parity.acquire.cta.shared::cta.b64 P, [%0], %1, 0x989680;\n\t"
                 "@P bra.uni WD_%=;\n\t"
                 "bra.uni WL_%=;\n\t"
                 "WD_%=:\n\t}"
                 :: "r"(mbar), "r"(phase) : "memory");
}
__device__ __forceinline__ void tma2d(uint32_t dst, const void* map, int x, int y, uint32_t mbar) {
    asm volatile("cp.async.bulk.tensor.2d.shared::cta.global.tile.mbarrier::complete_tx::bytes "
                 "[%0], [%1, {%2, %3}], [%4];"
                 :: "r"(dst), "l"(map), "r"(x), "r"(y), "r"(mbar) : "memory");
}

// ---------- kernel 1: gather (zgT transpose + identity block of zctx) ----------
__global__ void gather_kernel(const float* __restrict__ factors,
                              const int*   __restrict__ t_idx) {
    int gid = blockIdx.x * blockDim.x + threadIdx.x;
    if (gid < NCOL * NX) {
        int n = gid / NX, y = gid - n * NX;
        int t = n >> 2, zi = n & 3;
        g_zgT[gid] = factors[(size_t)t_idx[t] * NOUT + y * NZ + zi];
    } else {
        int i = gid - NCOL * NX;
        if (i < TT * NOUT / 4) {
            int t = i / (NOUT / 4);
            int j = i - t * (NOUT / 4);
            ((float4*)g_zctx)[(size_t)t * (KDIM / 4) + j] =
                ((const float4*)factors)[(size_t)t_idx[t] * (NOUT / 4) + j];
        }
    }
}

// ---------- kernel 2: relation GEMM (4000x2000)@(2000x64), k-paired FFMA2 ----------
#define KT1  100
#define PSTR 108
__global__ __launch_bounds__(256) void gemm1_kernel(const float* __restrict__ rel) {
    __shared__ float a_s[16 * PSTR];
    __shared__ float z_s[64 * PSTR];
    int tid = threadIdx.x;
    int lane = tid & 31, warp = tid >> 5;
    int mlow = (lane >> 2) & 7;
    int nb   = warp * 8 + (lane & 3) * 2;
    int mbase = blockIdx.x * 16;

    ull acc[2][2] = {{0, 0}, {0, 0}};

    for (int kt = 0; kt < NX; kt += KT1) {
        for (int idx = tid; idx < 400; idx += 256) {
            int row = idx / 25, q = idx - row * 25;
            *(float4*)&a_s[row * PSTR + q * 4] =
                *(const float4*)&rel[(size_t)(mbase + row) * NX + kt + q * 4];
        }
        for (int idx = tid; idx < 1600; idx += 256) {
            int row = idx / 25, q = idx - row * 25;
            *(float4*)&z_s[row * PSTR + q * 4] =
                *(const float4*)&g_zgT[(size_t)row * NX + kt + q * 4];
        }
        __syncthreads();

        #pragma unroll 5
        for (int kk = 0; kk < KT1; kk += 4) {
            ulonglong2 am[2], zn[2];
            am[0] = *(const ulonglong2*)&a_s[(mlow)     * PSTR + kk];
            am[1] = *(const ulonglong2*)&a_s[(mlow + 8) * PSTR + kk];
            zn[0] = *(const ulonglong2*)&z_s[(nb)       * PSTR + kk];
            zn[1] = *(const ulonglong2*)&z_s[(nb + 1)   * PSTR + kk];
            #pragma unroll
            for (int i = 0; i < 2; i++)
                #pragma unroll
                for (int j = 0; j < 2; j++) {
                    ffma2u(acc[i][j], am[i].x, zn[j].x);
                    ffma2u(acc[i][j], am[i].y, zn[j].y);
                }
        }
        __syncthreads();
    }
    #pragma unroll
    for (int i = 0; i < 2; i++)
        #pragma unroll
        for (int j = 0; j < 2; j++) {
            int m = mbase + mlow + 8 * i;
            int n = nb + j;
            int x = m >> 1, r = (m & 1) + 1;
            int t = n >> 2, zi = n & 3;
            F2U v; v.u = acc[i][j];
            g_zctx[(size_t)t * KDIM + r * NOUT + x * NZ + zi] = v.f.x + v.f.y;
        }
}

// ---------- kernel 3: MLP partial GEMM — 2D TMA, 3-stage pipeline ----------
// block 256 thr: 256 W-rows x 16 t, thread = 4 rows (stride 64) x 4 t (stride 4).
// stage: W 256x128B (SW128) + Z 16x128B = 34816 B; 3 stages = 104448 B, 2 blk/SM.
#define STAGES      3
#define STAGE_F     8704            // floats per stage
#define ZOFF_F      8192            // Z offset within stage (floats)
#define STAGE_BYTES 34816
#define MBAR_OFF    (STAGES * STAGE_BYTES)
#define SMEM_BYTES  (MBAR_OFF + 32)

__global__ __launch_bounds__(256, 2) void mlp_kernel(
        const __grid_constant__ CUtensorMap tmW,
        const __grid_constant__ CUtensorMap tmZ) {
    extern __shared__ __align__(1024) float sm[];
    uint32_t sb = s2u(sm);
    int tid = threadIdx.x;
    int tg  = tid & 3;            // t low
    int rid = tid >> 2;           // 0..63
    int rxor4 = (rid & 7) << 2;   // W swizzle XOR (in floats, chunk<<2)
    int zx0 = tg << 2, zx1 = (tg ^ 4) << 2;
    int rowblk = blockIdx.x, kb = blockIdx.y;

    int row0 = rowblk * 256;
    if (row0 > NOUT - 256) row0 = NOUT - 256;     // benign duplicate rows
    int t0 = kb * TPK;
    int t1 = t0 + TPK; if (t1 > NTILES) t1 = NTILES;
    int nt = t1 - t0;

    uint32_t mb = sb + MBAR_OFF;
    if (tid == 0) {
        #pragma unroll
        for (int s = 0; s < STAGES; s++) mbar_init(mb + 8 * s, 1);
    }
    __syncthreads();

    ull acc[4][4];
    #pragma unroll
    for (int i = 0; i < 4; i++)
        #pragma unroll
        for (int j = 0; j < 4; j++) acc[i][j] = 0;

    // prologue: fill all stages
    if (tid == 0) {
        #pragma unroll
        for (int s = 0; s < STAGES; s++) {
            if (s < nt) {
                int k0 = (t0 + s) * KT;
                uint32_t mbar = mb + 8 * s;
                mbar_expect(mbar, STAGE_BYTES);
                tma2d(sb + s * STAGE_BYTES,          &tmW, k0, row0, mbar);
                tma2d(sb + s * STAGE_BYTES + 32768,  &tmZ, k0, 0,    mbar);
            }
        }
    }

    int ph0 = 0, ph1 = 0, ph2 = 0;
    int s = 0;
    for (int it = 0; it < nt; it++) {
        if      (s == 0) { mbar_wait(mb,      ph0); ph0 ^= 1; }
        else if (s == 1) { mbar_wait(mb + 8,  ph1); ph1 ^= 1; }
        else             { mbar_wait(mb + 16, ph2); ph2 ^= 1; }

        const float* Wt = sm + s * STAGE_F;
        const float* Zt = Wt + ZOFF_F;
        #pragma unroll
        for (int kk = 0; kk < KT; kk += 4) {
            int ch = kk >> 2;
            int wc = ((ch << 2) ^ rxor4);            // = (ch ^ (rid&7))<<2
            ulonglong2 wv[4], zv[4];
            #pragma unroll
            for (int i = 0; i < 4; i++)
                wv[i] = *(const ulonglong2*)&Wt[(rid + 64 * i) * 32 + wc];
            int zc0 = ((ch << 2) ^ zx0);
            int zc1 = ((ch << 2) ^ zx1);
            zv[0] = *(const ulonglong2*)&Zt[(tg)      * 32 + zc0];
            zv[1] = *(const ulonglong2*)&Zt[(tg + 4)  * 32 + zc1];
            zv[2] = *(const ulonglong2*)&Zt[(tg + 8)  * 32 + zc0];
            zv[3] = *(const ulonglong2*)&Zt[(tg + 12) * 32 + zc1];
            #pragma unroll
            for (int i = 0; i < 4; i++)
                #pragma unroll
                for (int j = 0; j < 4; j++) {
                    ffma2u(acc[i][j], wv[i].x, zv[j].x);
                    ffma2u(acc[i][j], wv[i].y, zv[j].y);
                }
        }
        __syncthreads();          // all warps done with stage s
        if (it + STAGES < nt && tid == 0) {
            int k0 = (t0 + it + STAGES) * KT;
            uint32_t mbar = mb + 8 * s;
            mbar_expect(mbar, STAGE_BYTES);
            tma2d(sb + s * STAGE_BYTES,         &tmW, k0, row0, mbar);
            tma2d(sb + s * STAGE_BYTES + 32768, &tmZ, k0, 0,    mbar);
        }
        s = (s + 1 == STAGES) ? 0 : s + 1;
    }

    #pragma unroll
    for (int i = 0; i < 4; i++) {
        int row = row0 + rid + 64 * i;
        #pragma unroll
        for (int j = 0; j < 4; j++) {
            F2U v; v.u = acc[i][j];
            g_scratch[((size_t)kb * NOUT + row) * TT + tg + 4 * j] = v.f.x + v.f.y;
        }
    }
}

// ---------- kernel 4: epilogue — sum partials + bias + tanh ----------
__global__ void epilogue_kernel(const float* __restrict__ bias,
                                float* __restrict__ out) {
    int idx = blockIdx.x * blockDim.x + threadIdx.x;
    if (idx >= NOUT * 4) return;
    int n = idx >> 2, tq = idx & 3;
    float4 s = make_float4(0.f, 0.f, 0.f, 0.f);
    #pragma unroll
    for (int kb = 0; kb < KSPLIT; kb++) {
        float4 v = *(const float4*)&g_scratch[((size_t)kb * NOUT + n) * TT + tq * 4];
        s.x += v.x; s.y += v.y; s.z += v.z; s.w += v.w;
    }
    float b = bias[n];
    out[(size_t)(tq*4+0) * NOUT + n] = tanhf(s.x + b);
    out[(size_t)(tq*4+1) * NOUT + n] = tanhf(s.y + b);
    out[(size_t)(tq*4+2) * NOUT + n] = tanhf(s.z + b);
    out[(size_t)(tq*4+3) * NOUT + n] = tanhf(s.w + b);
}

// ---------- host ----------
typedef CUresult (*EncodeTiledFn)(
    CUtensorMap*, CUtensorMapDataType, cuuint32_t, void*,
    const cuuint64_t*, const cuuint64_t*, const cuuint32_t*, const cuuint32_t*,
    CUtensorMapInterleave, CUtensorMapSwizzle, CUtensorMapL2promotion,
    CUtensorMapFloatOOBfill);

extern "C" void kernel_launch(void* const* d_in, const int* in_sizes, int n_in,
                              void* d_out, int out_size) {
    const float* relations = (const float*)d_in[0];
    const float* factors   = (const float*)d_in[1];
    const float* W_dyn     = (const float*)d_in[2];
    const float* b_dyn     = (const float*)d_in[3];
    const int*   t_idx     = (const int*)d_in[4];
    float* out = (float*)d_out;

    // build tensor maps (host-side, no allocation, capture-safe)
    void* fn = nullptr;
    cudaDriverEntryPointQueryResult qr;
    cudaGetDriverEntryPoint("cuTensorMapEncodeTiled", &fn, cudaEnableDefault, &qr);
    EncodeTiledFn encode = (EncodeTiledFn)fn;

    CUtensorMap tmW, tmZ;
    {
        cuuint64_t dims[2]    = {KDIM, NOUT};
        cuuint64_t strides[1] = {KDIM * 4};
        cuuint32_t box[2]     = {32, 256};
        cuuint32_t estr[2]    = {1, 1};
        encode(&tmW, CU_TENSOR_MAP_DATA_TYPE_FLOAT32, 2, (void*)W_dyn,
               dims, strides, box, estr,
               CU_TENSOR_MAP_INTERLEAVE_NONE, CU_TENSOR_MAP_SWIZZLE_128B,
               CU_TENSOR_MAP_L2_PROMOTION_L2_128B, CU_TENSOR_MAP_FLOAT_OOB_FILL_NONE);
    }
    {
        void* zaddr = nullptr;
        cudaGetSymbolAddress(&zaddr, g_zctx);
        cuuint64_t dims[2]    = {KDIM, TT};
        cuuint64_t strides[1] = {KDIM * 4};
        cuuint32_t box[2]     = {32, 16};
        cuuint32_t estr[2]    = {1, 1};
        encode(&tmZ, CU_TENSOR_MAP_DATA_TYPE_FLOAT32, 2, zaddr,
               dims, strides, box, estr,
               CU_TENSOR_MAP_INTERLEAVE_NONE, CU_TENSOR_MAP_SWIZZLE_128B,
               CU_TENSOR_MAP_L2_PROMOTION_L2_128B, CU_TENSOR_MAP_FLOAT_OOB_FILL_NONE);
    }

    cudaFuncSetAttribute(mlp_kernel, cudaFuncAttributeMaxDynamicSharedMemorySize, SMEM_BYTES);

    gather_kernel<<<625, 256>>>(factors, t_idx);
    gemm1_kernel<<<250, 256>>>(relations);
    dim3 grid(32, KSPLIT);      // 32 row-blocks x 9 k-splits
    mlp_kernel<<<grid, 256, SMEM_BYTES>>>(tmW, tmZ);
    epilogue_kernel<<<(NOUT * 4 + 255) / 256, 256>>>(b_dyn, out);
}

// round 12
// speedup vs baseline: 1.9264x; 1.3724x over previous
#include <cuda_runtime.h>
#include <cuda.h>
#include <math.h>
#include <stdint.h>

#define NX    2000
#define NZ    4
#define TT    16
#define KDIM  24000   // 3*2000*4
#define NOUT  8000    // nz*nx
#define NCOL  64      // TT*NZ

#define KSPLIT 9
#define KT     32
#define NTILES (KDIM / KT)        // 750
#define TPK    84                 // ceil(750/9)

#define M1    4000                // relations rows
#define K1    2000
#define G1TILES 63                // ceil(2000/32), last tile OOB zero-filled
#define G1KB  4

__device__ float g_zctx[TT * KDIM];              // (16, 24000) row-major
__device__ float g_zgT[NCOL * NX];               // [n][y], n = t*4+z
__device__ float g_scratch[KSPLIT * NOUT * TT];  // mlp partials; reused for gemm1 partials

typedef unsigned long long ull;
union F2U { float2 f; ull u; };
__device__ __forceinline__ void ffma2u(ull& d, ull a, ull b) {
    asm("fma.rn.f32x2 %0, %1, %2, %0;" : "+l"(d) : "l"(a), "l"(b));
}
__device__ __forceinline__ uint32_t s2u(const void* p) {
    uint32_t a;
    asm("{ .reg .u64 t; cvta.to.shared.u64 t, %1; cvt.u32.u64 %0, t; }" : "=r"(a) : "l"(p));
    return a;
}
__device__ __forceinline__ void mbar_init(uint32_t mbar, int cnt) {
    asm volatile("mbarrier.init.shared.b64 [%0], %1;" :: "r"(mbar), "r"(cnt) : "memory");
}
__device__ __forceinline__ void mbar_expect(uint32_t mbar, int bytes) {
    asm volatile("mbarrier.arrive.expect_tx.shared.b64 _, [%0], %1;" :: "r"(mbar), "r"(bytes) : "memory");
}
__device__ __forceinline__ void mbar_wait(uint32_t mbar, int phase) {
    asm volatile("{\n\t.reg .pred P;\n\t"
                 "WL_%=:\n\t"
                 "mbarrier.try_wait.parity.acquire.cta.shared::cta.b64 P, [%0], %1, 0x989680;\n\t"
                 "@P bra.uni WD_%=;\n\t"
                 "bra.uni WL_%=;\n\t"
                 "WD_%=:\n\t}"
                 :: "r"(mbar), "r"(phase) : "memory");
}
__device__ __forceinline__ void tma2d(uint32_t dst, const void* map, int x, int y, uint32_t mbar) {
    asm volatile("cp.async.bulk.tensor.2d.shared::cta.global.tile.mbarrier::complete_tx::bytes "
                 "[%0], [%1, {%2, %3}], [%4];"
                 :: "r"(dst), "l"(map), "r"(x), "r"(y), "r"(mbar) : "memory");
}

// ---------- kernel 1: gather (zgT transpose + identity block of zctx) ----------
__global__ void gather_kernel(const float* __restrict__ factors,
                              const int*   __restrict__ t_idx) {
    int gid = blockIdx.x * blockDim.x + threadIdx.x;
    if (gid < NCOL * NX) {
        int n = gid / NX, y = gid - n * NX;
        int t = n >> 2, zi = n & 3;
        g_zgT[gid] = factors[(size_t)t_idx[t] * NOUT + y * NZ + zi];
    } else {
        int i = gid - NCOL * NX;
        if (i < TT * NOUT / 4) {
            int t = i / (NOUT / 4);
            int j = i - t * (NOUT / 4);
            ((float4*)g_zctx)[(size_t)t * (KDIM / 4) + j] =
                ((const float4*)factors)[(size_t)t_idx[t] * (NOUT / 4) + j];
        }
    }
}

// ---------- kernel 2: relation GEMM via TMA pipeline ----------
// C (4000x64) = rel (4000x2000) @ zgT^T.  block = 64 m x 64 n, thread = 4m x 4n.
// stage: A 64x128B + B 64x128B = 16384 B, 3 stages.
#define G1_STAGES      3
#define G1_STAGE_F     4096
#define G1_STAGE_BYTES 16384
#define G1_MBAR_OFF    (G1_STAGES * G1_STAGE_BYTES)
#define G1_SMEM        (G1_MBAR_OFF + 32)

__global__ __launch_bounds__(256) void gemm1_kernel(
        const __grid_constant__ CUtensorMap tmA,
        const __grid_constant__ CUtensorMap tmB) {
    extern __shared__ __align__(1024) float sm1[];
    uint32_t sb = s2u(sm1);
    int tid = threadIdx.x;
    int nl = tid & 15, rid0 = tid >> 4;       // 16 n-lanes x 16 row-groups
    int row0 = blockIdx.x * 64;
    if (row0 > M1 - 64) row0 = M1 - 64;       // benign duplicates
    int kb = blockIdx.y;
    int t0 = kb * 16, t1 = t0 + 16; if (t1 > G1TILES) t1 = G1TILES;
    int nt = t1 - t0;

    uint32_t mb = sb + G1_MBAR_OFF;
    if (tid == 0) {
        #pragma unroll
        for (int s = 0; s < G1_STAGES; s++) mbar_init(mb + 8 * s, 1);
    }
    __syncthreads();

    ull acc[4][4];
    #pragma unroll
    for (int i = 0; i < 4; i++)
        #pragma unroll
        for (int j = 0; j < 4; j++) acc[i][j] = 0;

    if (tid == 0) {
        #pragma unroll
        for (int s = 0; s < G1_STAGES; s++) {
            if (s < nt) {
                int k0 = (t0 + s) * 32;
                uint32_t mbar = mb + 8 * s;
                mbar_expect(mbar, G1_STAGE_BYTES);
                tma2d(sb + s * G1_STAGE_BYTES,        &tmA, k0, row0, mbar);
                tma2d(sb + s * G1_STAGE_BYTES + 8192, &tmB, k0, 0,    mbar);
            }
        }
    }

    int axor = (rid0 & 7) << 2;
    int bxor = (nl & 7) << 2;
    int ph0 = 0, ph1 = 0, ph2 = 0;
    int s = 0;
    for (int it = 0; it < nt; it++) {
        if      (s == 0) { mbar_wait(mb,      ph0); ph0 ^= 1; }
        else if (s == 1) { mbar_wait(mb + 8,  ph1); ph1 ^= 1; }
        else             { mbar_wait(mb + 16, ph2); ph2 ^= 1; }

        const float* As = sm1 + s * G1_STAGE_F;
        const float* Bs = As + 2048;
        #pragma unroll
        for (int kk = 0; kk < 32; kk += 4) {
            int ch = kk >> 2;
            int wc = (ch << 2) ^ axor;
            int bc = (ch << 2) ^ bxor;
            ulonglong2 av[4], bv[4];
            #pragma unroll
            for (int i = 0; i < 4; i++)
                av[i] = *(const ulonglong2*)&As[(rid0 + 16 * i) * 32 + wc];
            #pragma unroll
            for (int j = 0; j < 4; j++)
                bv[j] = *(const ulonglong2*)&Bs[(nl + 16 * j) * 32 + bc];
            #pragma unroll
            for (int i = 0; i < 4; i++)
                #pragma unroll
                for (int j = 0; j < 4; j++) {
                    ffma2u(acc[i][j], av[i].x, bv[j].x);
                    ffma2u(acc[i][j], av[i].y, bv[j].y);
                }
        }
        __syncthreads();
        if (it + G1_STAGES < nt && tid == 0) {
            int k0 = (t0 + it + G1_STAGES) * 32;
            uint32_t mbar = mb + 8 * s;
            mbar_expect(mbar, G1_STAGE_BYTES);
            tma2d(sb + s * G1_STAGE_BYTES,        &tmA, k0, row0, mbar);
            tma2d(sb + s * G1_STAGE_BYTES + 8192, &tmB, k0, 0,    mbar);
        }
        s = (s + 1 == G1_STAGES) ? 0 : s + 1;
    }

    #pragma unroll
    for (int i = 0; i < 4; i++) {
        int row = row0 + rid0 + 16 * i;
        #pragma unroll
        for (int j = 0; j < 4; j++) {
            F2U v; v.u = acc[i][j];
            g_scratch[((size_t)kb * M1 + row) * 64 + nl + 16 * j] = v.f.x + v.f.y;
        }
    }
}

// ---------- kernel 2.5: merge gemm1 partials, scatter into zctx ----------
__global__ void merge_kernel() {
    int idx = blockIdx.x * blockDim.x + threadIdx.x;
    if (idx >= M1 * 64) return;
    int m = idx >> 6, n = idx & 63;
    float s = 0.f;
    #pragma unroll
    for (int kb = 0; kb < G1KB; kb++)
        s += g_scratch[((size_t)kb * M1 + m) * 64 + n];
    int x = m >> 1, r = (m & 1) + 1;
    int t = n >> 2, zi = n & 3;
    g_zctx[(size_t)t * KDIM + r * NOUT + x * NZ + zi] = s;
}

// ---------- kernel 3: MLP partial GEMM — 2D TMA, 3-stage pipeline ----------
#define STAGES      3
#define STAGE_F     8704
#define ZOFF_F      8192
#define STAGE_BYTES 34816
#define MBAR_OFF    (STAGES * STAGE_BYTES)
#define SMEM_BYTES  (MBAR_OFF + 32)

__global__ __launch_bounds__(256, 2) void mlp_kernel(
        const __grid_constant__ CUtensorMap tmW,
        const __grid_constant__ CUtensorMap tmZ) {
    extern __shared__ __align__(1024) float sm[];
    uint32_t sb = s2u(sm);
    int tid = threadIdx.x;
    int tg  = tid & 3;
    int rid = tid >> 2;
    int rxor4 = (rid & 7) << 2;
    int zx0 = tg << 2, zx1 = (tg ^ 4) << 2;
    int rowblk = blockIdx.x, kb = blockIdx.y;

    int row0 = rowblk * 256;
    if (row0 > NOUT - 256) row0 = NOUT - 256;
    int t0 = kb * TPK;
    int t1 = t0 + TPK; if (t1 > NTILES) t1 = NTILES;
    int nt = t1 - t0;

    uint32_t mb = sb + MBAR_OFF;
    if (tid == 0) {
        #pragma unroll
        for (int s = 0; s < STAGES; s++) mbar_init(mb + 8 * s, 1);
    }
    __syncthreads();

    ull acc[4][4];
    #pragma unroll
    for (int i = 0; i < 4; i++)
        #pragma unroll
        for (int j = 0; j < 4; j++) acc[i][j] = 0;

    if (tid == 0) {
        #pragma unroll
        for (int s = 0; s < STAGES; s++) {
            if (s < nt) {
                int k0 = (t0 + s) * KT;
                uint32_t mbar = mb + 8 * s;
                mbar_expect(mbar, STAGE_BYTES);
                tma2d(sb + s * STAGE_BYTES,         &tmW, k0, row0, mbar);
                tma2d(sb + s * STAGE_BYTES + 32768, &tmZ, k0, 0,    mbar);
            }
        }
    }

    int ph0 = 0, ph1 = 0, ph2 = 0;
    int s = 0;
    for (int it = 0; it < nt; it++) {
        if      (s == 0) { mbar_wait(mb,      ph0); ph0 ^= 1; }
        else if (s == 1) { mbar_wait(mb + 8,  ph1); ph1 ^= 1; }
        else             { mbar_wait(mb + 16, ph2); ph2 ^= 1; }

        const float* Wt = sm + s * STAGE_F;
        const float* Zt = Wt + ZOFF_F;
        #pragma unroll
        for (int kk = 0; kk < KT; kk += 4) {
            int ch = kk >> 2;
            int wc = (ch << 2) ^ rxor4;
            ulonglong2 wv[4], zv[4];
            #pragma unroll
            for (int i = 0; i < 4; i++)
                wv[i] = *(const ulonglong2*)&Wt[(rid + 64 * i) * 32 + wc];
            int zc0 = (ch << 2) ^ zx0;
            int zc1 = (ch << 2) ^ zx1;
            zv[0] = *(const ulonglong2*)&Zt[(tg)      * 32 + zc0];
            zv[1] = *(const ulonglong2*)&Zt[(tg + 4)  * 32 + zc1];
            zv[2] = *(const ulonglong2*)&Zt[(tg + 8)  * 32 + zc0];
            zv[3] = *(const ulonglong2*)&Zt[(tg + 12) * 32 + zc1];
            #pragma unroll
            for (int i = 0; i < 4; i++)
                #pragma unroll
                for (int j = 0; j < 4; j++) {
                    ffma2u(acc[i][j], wv[i].x, zv[j].x);
                    ffma2u(acc[i][j], wv[i].y, zv[j].y);
                }
        }
        __syncthreads();
        if (it + STAGES < nt && tid == 0) {
            int k0 = (t0 + it + STAGES) * KT;
            uint32_t mbar = mb + 8 * s;
            mbar_expect(mbar, STAGE_BYTES);
            tma2d(sb + s * STAGE_BYTES,         &tmW, k0, row0, mbar);
            tma2d(sb + s * STAGE_BYTES + 32768, &tmZ, k0, 0,    mbar);
        }
        s = (s + 1 == STAGES) ? 0 : s + 1;
    }

    #pragma unroll
    for (int i = 0; i < 4; i++) {
        int row = row0 + rid + 64 * i;
        #pragma unroll
        for (int j = 0; j < 4; j++) {
            F2U v; v.u = acc[i][j];
            g_scratch[((size_t)kb * NOUT + row) * TT + tg + 4 * j] = v.f.x + v.f.y;
        }
    }
}

// ---------- kernel 4: epilogue — sum partials + bias + tanh ----------
__global__ void epilogue_kernel(const float* __restrict__ bias,
                                float* __restrict__ out) {
    int idx = blockIdx.x * blockDim.x + threadIdx.x;
    if (idx >= NOUT * 4) return;
    int n = idx >> 2, tq = idx & 3;
    float4 s = make_float4(0.f, 0.f, 0.f, 0.f);
    #pragma unroll
    for (int kb = 0; kb < KSPLIT; kb++) {
        float4 v = *(const float4*)&g_scratch[((size_t)kb * NOUT + n) * TT + tq * 4];
        s.x += v.x; s.y += v.y; s.z += v.z; s.w += v.w;
    }
    float b = bias[n];
    out[(size_t)(tq*4+0) * NOUT + n] = tanhf(s.x + b);
    out[(size_t)(tq*4+1) * NOUT + n] = tanhf(s.y + b);
    out[(size_t)(tq*4+2) * NOUT + n] = tanhf(s.z + b);
    out[(size_t)(tq*4+3) * NOUT + n] = tanhf(s.w + b);
}

// ---------- host ----------
typedef CUresult (*EncodeTiledFn)(
    CUtensorMap*, CUtensorMapDataType, cuuint32_t, void*,
    const cuuint64_t*, const cuuint64_t*, const cuuint32_t*, const cuuint32_t*,
    CUtensorMapInterleave, CUtensorMapSwizzle, CUtensorMapL2promotion,
    CUtensorMapFloatOOBfill);

static void make_map2d(EncodeTiledFn encode, CUtensorMap* tm, void* base,
                       cuuint64_t dimx, cuuint64_t dimy,
                       cuuint32_t boxx, cuuint32_t boxy) {
    cuuint64_t dims[2]    = {dimx, dimy};
    cuuint64_t strides[1] = {dimx * 4};
    cuuint32_t box[2]     = {boxx, boxy};
    cuuint32_t estr[2]    = {1, 1};
    encode(tm, CU_TENSOR_MAP_DATA_TYPE_FLOAT32, 2, base,
           dims, strides, box, estr,
           CU_TENSOR_MAP_INTERLEAVE_NONE, CU_TENSOR_MAP_SWIZZLE_128B,
           CU_TENSOR_MAP_L2_PROMOTION_L2_128B, CU_TENSOR_MAP_FLOAT_OOB_FILL_NONE);
}

extern "C" void kernel_launch(void* const* d_in, const int* in_sizes, int n_in,
                              void* d_out, int out_size) {
    const float* relations = (const float*)d_in[0];
    const float* factors   = (const float*)d_in[1];
    const float* W_dyn     = (const float*)d_in[2];
    const float* b_dyn     = (const float*)d_in[3];
    const int*   t_idx     = (const int*)d_in[4];
    float* out = (float*)d_out;

    void* fn = nullptr;
    cudaDriverEntryPointQueryResult qr;
    cudaGetDriverEntryPoint("cuTensorMapEncodeTiled", &fn, cudaEnableDefault, &qr);
    EncodeTiledFn encode = (EncodeTiledFn)fn;

    void* zaddr = nullptr;  cudaGetSymbolAddress(&zaddr, g_zctx);
    void* zgaddr = nullptr; cudaGetSymbolAddress(&zgaddr, g_zgT);

    CUtensorMap tmW, tmZ, tmA, tmB;
    make_map2d(encode, &tmW, (void*)W_dyn,     KDIM, NOUT, 32, 256);
    make_map2d(encode, &tmZ, zaddr,            KDIM, TT,   32, 16);
    make_map2d(encode, &tmA, (void*)relations, K1,   M1,   32, 64);
    make_map2d(encode, &tmB, zgaddr,           K1,   NCOL, 32, 64);

    cudaFuncSetAttribute(mlp_kernel,   cudaFuncAttributeMaxDynamicSharedMemorySize, SMEM_BYTES);
    cudaFuncSetAttribute(gemm1_kernel, cudaFuncAttributeMaxDynamicSharedMemorySize, G1_SMEM);

    gather_kernel<<<625, 256>>>(factors, t_idx);
    dim3 g1(63, G1KB);
    gemm1_kernel<<<g1, 256, G1_SMEM>>>(tmA, tmB);
    merge_kernel<<<(M1 * 64 + 255) / 256, 256>>>();
    dim3 grid(32, KSPLIT);
    mlp_kernel<<<grid, 256, SMEM_BYTES>>>(tmW, tmZ);
    epilogue_kernel<<<(NOUT * 4 + 255) / 256, 256>>>(b_dyn, out);
}

// round 13
// speedup vs baseline: 2.0553x; 1.0669x over previous
#include <cuda_runtime.h>
#include <cuda.h>
#include <math.h>
#include <stdint.h>

#define NX    2000
#define NZ    4
#define TT    16
#define KDIM  24000   // 3*2000*4
#define NOUT  8000    // nz*nx
#define NCOL  64      // TT*NZ

#define KSPLIT 9
#define KT     32
#define NTILES (KDIM / KT)        // 750
#define TPK    84                 // ceil(750/9)

#define M1    4000                // relations rows
#define K1    2000
#define G1TILES 63                // ceil(2000/32), last tile OOB zero-filled
#define G1KB  4

__device__ float g_zctx[TT * KDIM];              // (16, 24000) row-major
__device__ float g_zgT[NCOL * NX];               // [n][y], n = t*4+z
__device__ float g_scratch[KSPLIT * NOUT * TT];  // mlp partials; reused for gemm1 partials

typedef unsigned long long ull;
union F2U { float2 f; ull u; };
__device__ __forceinline__ void ffma2u(ull& d, ull a, ull b) {
    asm("fma.rn.f32x2 %0, %1, %2, %0;" : "+l"(d) : "l"(a), "l"(b));
}
__device__ __forceinline__ uint32_t s2u(const void* p) {
    uint32_t a;
    asm("{ .reg .u64 t; cvta.to.shared.u64 t, %1; cvt.u32.u64 %0, t; }" : "=r"(a) : "l"(p));
    return a;
}
__device__ __forceinline__ void mbar_init(uint32_t mbar, int cnt) {
    asm volatile("mbarrier.init.shared.b64 [%0], %1;" :: "r"(mbar), "r"(cnt) : "memory");
}
__device__ __forceinline__ void mbar_expect(uint32_t mbar, int bytes) {
    asm volatile("mbarrier.arrive.expect_tx.shared.b64 _, [%0], %1;" :: "r"(mbar), "r"(bytes) : "memory");
}
__device__ __forceinline__ void mbar_wait(uint32_t mbar, int phase) {
    asm volatile("{\n\t.reg .pred P;\n\t"
                 "WL_%=:\n\t"
                 "mbarrier.try_wait.parity.acquire.cta.shared::cta.b64 P, [%0], %1, 0x989680;\n\t"
                 "@P bra.uni WD_%=;\n\t"
                 "bra.uni WL_%=;\n\t"
                 "WD_%=:\n\t}"
                 :: "r"(mbar), "r"(phase) : "memory");
}
__device__ __forceinline__ void tma2d(uint32_t dst, const void* map, int x, int y, uint32_t mbar) {
    asm volatile("cp.async.bulk.tensor.2d.shared::cta.global.tile.mbarrier::complete_tx::bytes "
                 "[%0], [%1, {%2, %3}], [%4];"
                 :: "r"(dst), "l"(map), "r"(x), "r"(y), "r"(mbar) : "memory");
}

// ---------- kernel 1: gather (zgT transpose + identity block of zctx) ----------
__global__ void gather_kernel(const float* __restrict__ factors,
                              const int*   __restrict__ t_idx) {
    int gid = blockIdx.x * blockDim.x + threadIdx.x;
    if (gid < NCOL * NX) {
        int n = gid / NX, y = gid - n * NX;
        int t = n >> 2, zi = n & 3;
        g_zgT[gid] = factors[(size_t)t_idx[t] * NOUT + y * NZ + zi];
    } else {
        int i = gid - NCOL * NX;
        if (i < TT * NOUT / 4) {
            int t = i / (NOUT / 4);
            int j = i - t * (NOUT / 4);
            ((float4*)g_zctx)[(size_t)t * (KDIM / 4) + j] =
                ((const float4*)factors)[(size_t)t_idx[t] * (NOUT / 4) + j];
        }
    }
}

// ---------- kernel 2: relation GEMM via TMA pipeline ----------
#define G1_STAGES      3
#define G1_STAGE_F     4096
#define G1_STAGE_BYTES 16384
#define G1_MBAR_OFF    (G1_STAGES * G1_STAGE_BYTES)
#define G1_SMEM        (G1_MBAR_OFF + 32)

__global__ __launch_bounds__(256) void gemm1_kernel(
        const __grid_constant__ CUtensorMap tmA,
        const __grid_constant__ CUtensorMap tmB) {
    extern __shared__ __align__(1024) float sm1[];
    uint32_t sb = s2u(sm1);
    int tid = threadIdx.x;
    int nl = tid & 15, rid0 = tid >> 4;
    int row0 = blockIdx.x * 64;
    if (row0 > M1 - 64) row0 = M1 - 64;
    int kb = blockIdx.y;
    int t0 = kb * 16, t1 = t0 + 16; if (t1 > G1TILES) t1 = G1TILES;
    int nt = t1 - t0;

    uint32_t mb = sb + G1_MBAR_OFF;
    if (tid == 0) {
        #pragma unroll
        for (int s = 0; s < G1_STAGES; s++) mbar_init(mb + 8 * s, 1);
    }
    __syncthreads();

    ull acc[4][4];
    #pragma unroll
    for (int i = 0; i < 4; i++)
        #pragma unroll
        for (int j = 0; j < 4; j++) acc[i][j] = 0;

    if (tid == 0) {
        #pragma unroll
        for (int s = 0; s < G1_STAGES; s++) {
            if (s < nt) {
                int k0 = (t0 + s) * 32;
                uint32_t mbar = mb + 8 * s;
                mbar_expect(mbar, G1_STAGE_BYTES);
                tma2d(sb + s * G1_STAGE_BYTES,        &tmA, k0, row0, mbar);
                tma2d(sb + s * G1_STAGE_BYTES + 8192, &tmB, k0, 0,    mbar);
            }
        }
    }

    int axor = (rid0 & 7) << 2;
    int bxor = (nl & 7) << 2;
    int ph0 = 0, ph1 = 0, ph2 = 0;
    int s = 0;
    for (int it = 0; it < nt; it++) {
        if      (s == 0) { mbar_wait(mb,      ph0); ph0 ^= 1; }
        else if (s == 1) { mbar_wait(mb + 8,  ph1); ph1 ^= 1; }
        else             { mbar_wait(mb + 16, ph2); ph2 ^= 1; }

        const float* As = sm1 + s * G1_STAGE_F;
        const float* Bs = As + 2048;
        #pragma unroll
        for (int kk = 0; kk < 32; kk += 4) {
            int ch = kk >> 2;
            int wc = (ch << 2) ^ axor;
            int bc = (ch << 2) ^ bxor;
            ulonglong2 av[4], bv[4];
            #pragma unroll
            for (int i = 0; i < 4; i++)
                av[i] = *(const ulonglong2*)&As[(rid0 + 16 * i) * 32 + wc];
            #pragma unroll
            for (int j = 0; j < 4; j++)
                bv[j] = *(const ulonglong2*)&Bs[(nl + 16 * j) * 32 + bc];
            #pragma unroll
            for (int i = 0; i < 4; i++)
                #pragma unroll
                for (int j = 0; j < 4; j++) {
                    ffma2u(acc[i][j], av[i].x, bv[j].x);
                    ffma2u(acc[i][j], av[i].y, bv[j].y);
                }
        }
        __syncthreads();
        if (it + G1_STAGES < nt && tid == 0) {
            int k0 = (t0 + it + G1_STAGES) * 32;
            uint32_t mbar = mb + 8 * s;
            mbar_expect(mbar, G1_STAGE_BYTES);
            tma2d(sb + s * G1_STAGE_BYTES,        &tmA, k0, row0, mbar);
            tma2d(sb + s * G1_STAGE_BYTES + 8192, &tmB, k0, 0,    mbar);
        }
        s = (s + 1 == G1_STAGES) ? 0 : s + 1;
    }

    #pragma unroll
    for (int i = 0; i < 4; i++) {
        int row = row0 + rid0 + 16 * i;
        #pragma unroll
        for (int j = 0; j < 4; j++) {
            F2U v; v.u = acc[i][j];
            g_scratch[((size_t)kb * M1 + row) * 64 + nl + 16 * j] = v.f.x + v.f.y;
        }
    }
}

// ---------- kernel 2.5: merge gemm1 partials, scatter into zctx ----------
__global__ void merge_kernel() {
    int idx = blockIdx.x * blockDim.x + threadIdx.x;
    if (idx >= M1 * 64) return;
    int m = idx >> 6, n = idx & 63;
    float s = 0.f;
    #pragma unroll
    for (int kb = 0; kb < G1KB; kb++)
        s += g_scratch[((size_t)kb * M1 + m) * 64 + n];
    int x = m >> 1, r = (m & 1) + 1;
    int t = n >> 2, zi = n & 3;
    g_zctx[(size_t)t * KDIM + r * NOUT + x * NZ + zi] = s;
}

// ---------- kernel 3: MLP partial GEMM — 512-row blocks, 8x4 thread tile ----------
// block 256 thr covers 512 W-rows x 16 t; thread = 8 rows (stride 64) x 4 t (stride 4).
// stage: W 512x128B + Z 16x128B = 67584 B; 3 stages = 202752 B -> 1 block/SM.
#define STAGES      3
#define STAGE_F     16896
#define ZOFF_F      16384
#define STAGE_BYTES 67584
#define MBAR_OFF    (STAGES * STAGE_BYTES)
#define SMEM_BYTES  (MBAR_OFF + 32)

__global__ __launch_bounds__(256, 1) void mlp_kernel(
        const __grid_constant__ CUtensorMap tmW,
        const __grid_constant__ CUtensorMap tmZ) {
    extern __shared__ __align__(1024) float sm[];
    uint32_t sb = s2u(sm);
    int tid = threadIdx.x;
    int tg  = tid & 3;
    int rid = tid >> 2;           // 0..63
    int rxor4 = (rid & 7) << 2;
    int zx0 = tg << 2, zx1 = (tg ^ 4) << 2;
    int rowblk = blockIdx.x, kb = blockIdx.y;

    int row0 = rowblk * 512;
    if (row0 > NOUT - 512) row0 = NOUT - 512;     // benign duplicate rows
    int t0 = kb * TPK;
    int t1 = t0 + TPK; if (t1 > NTILES) t1 = NTILES;
    int nt = t1 - t0;

    uint32_t mb = sb + MBAR_OFF;
    if (tid == 0) {
        #pragma unroll
        for (int s = 0; s < STAGES; s++) mbar_init(mb + 8 * s, 1);
    }
    __syncthreads();

    ull acc[8][4];
    #pragma unroll
    for (int i = 0; i < 8; i++)
        #pragma unroll
        for (int j = 0; j < 4; j++) acc[i][j] = 0;

    if (tid == 0) {
        #pragma unroll
        for (int s = 0; s < STAGES; s++) {
            if (s < nt) {
                int k0 = (t0 + s) * KT;
                uint32_t mbar = mb + 8 * s;
                mbar_expect(mbar, STAGE_BYTES);
                tma2d(sb + s * STAGE_BYTES,         &tmW, k0, row0,       mbar);
                tma2d(sb + s * STAGE_BYTES + 32768, &tmW, k0, row0 + 256, mbar);
                tma2d(sb + s * STAGE_BYTES + 65536, &tmZ, k0, 0,          mbar);
            }
        }
    }

    int ph0 = 0, ph1 = 0, ph2 = 0;
    int s = 0;
    for (int it = 0; it < nt; it++) {
        if      (s == 0) { mbar_wait(mb,      ph0); ph0 ^= 1; }
        else if (s == 1) { mbar_wait(mb + 8,  ph1); ph1 ^= 1; }
        else             { mbar_wait(mb + 16, ph2); ph2 ^= 1; }

        const float* Wt = sm + s * STAGE_F;
        const float* Zt = Wt + ZOFF_F;
        #pragma unroll
        for (int kk = 0; kk < KT; kk += 4) {
            int ch = kk >> 2;
            int wc = (ch << 2) ^ rxor4;
            ulonglong2 wv[8], zv[4];
            #pragma unroll
            for (int i = 0; i < 8; i++)
                wv[i] = *(const ulonglong2*)&Wt[(rid + 64 * i) * 32 + wc];
            int zc0 = (ch << 2) ^ zx0;
            int zc1 = (ch << 2) ^ zx1;
            zv[0] = *(const ulonglong2*)&Zt[(tg)      * 32 + zc0];
            zv[1] = *(const ulonglong2*)&Zt[(tg + 4)  * 32 + zc1];
            zv[2] = *(const ulonglong2*)&Zt[(tg + 8)  * 32 + zc0];
            zv[3] = *(const ulonglong2*)&Zt[(tg + 12) * 32 + zc1];
            #pragma unroll
            for (int i = 0; i < 8; i++)
                #pragma unroll
                for (int j = 0; j < 4; j++) {
                    ffma2u(acc[i][j], wv[i].x, zv[j].x);
                    ffma2u(acc[i][j], wv[i].y, zv[j].y);
                }
        }
        __syncthreads();
        if (it + STAGES < nt && tid == 0) {
            int k0 = (t0 + it + STAGES) * KT;
            uint32_t mbar = mb + 8 * s;
            mbar_expect(mbar, STAGE_BYTES);
            tma2d(sb + s * STAGE_BYTES,         &tmW, k0, row0,       mbar);
            tma2d(sb + s * STAGE_BYTES + 32768, &tmW, k0, row0 + 256, mbar);
            tma2d(sb + s * STAGE_BYTES + 65536, &tmZ, k0, 0,          mbar);
        }
        s = (s + 1 == STAGES) ? 0 : s + 1;
    }

    #pragma unroll
    for (int i = 0; i < 8; i++) {
        int row = row0 + rid + 64 * i;
        #pragma unroll
        for (int j = 0; j < 4; j++) {
            F2U v; v.u = acc[i][j];
            g_scratch[((size_t)kb * NOUT + row) * TT + tg + 4 * j] = v.f.x + v.f.y;
        }
    }
}

// ---------- kernel 4: epilogue — sum partials + bias + tanh ----------
__global__ void epilogue_kernel(const float* __restrict__ bias,
                                float* __restrict__ out) {
    int idx = blockIdx.x * blockDim.x + threadIdx.x;
    if (idx >= NOUT * 4) return;
    int n = idx >> 2, tq = idx & 3;
    float4 s = make_float4(0.f, 0.f, 0.f, 0.f);
    #pragma unroll
    for (int kb = 0; kb < KSPLIT; kb++) {
        float4 v = *(const float4*)&g_scratch[((size_t)kb * NOUT + n) * TT + tq * 4];
        s.x += v.x; s.y += v.y; s.z += v.z; s.w += v.w;
    }
    float b = bias[n];
    out[(size_t)(tq*4+0) * NOUT + n] = tanhf(s.x + b);
    out[(size_t)(tq*4+1) * NOUT + n] = tanhf(s.y + b);
    out[(size_t)(tq*4+2) * NOUT + n] = tanhf(s.z + b);
    out[(size_t)(tq*4+3) * NOUT + n] = tanhf(s.w + b);
}

// ---------- host ----------
typedef CUresult (*EncodeTiledFn)(
    CUtensorMap*, CUtensorMapDataType, cuuint32_t, void*,
    const cuuint64_t*, const cuuint64_t*, const cuuint32_t*, const cuuint32_t*,
    CUtensorMapInterleave, CUtensorMapSwizzle, CUtensorMapL2promotion,
    CUtensorMapFloatOOBfill);

static void make_map2d(EncodeTiledFn encode, CUtensorMap* tm, void* base,
                       cuuint64_t dimx, cuuint64_t dimy,
                       cuuint32_t boxx, cuuint32_t boxy) {
    cuuint64_t dims[2]    = {dimx, dimy};
    cuuint64_t strides[1] = {dimx * 4};
    cuuint32_t box[2]     = {boxx, boxy};
    cuuint32_t estr[2]    = {1, 1};
    encode(tm, CU_TENSOR_MAP_DATA_TYPE_FLOAT32, 2, base,
           dims, strides, box, estr,
           CU_TENSOR_MAP_INTERLEAVE_NONE, CU_TENSOR_MAP_SWIZZLE_128B,
           CU_TENSOR_MAP_L2_PROMOTION_L2_128B, CU_TENSOR_MAP_FLOAT_OOB_FILL_NONE);
}

extern "C" void kernel_launch(void* const* d_in, const int* in_sizes, int n_in,
                              void* d_out, int out_size) {
    const float* relations = (const float*)d_in[0];
    const float* factors   = (const float*)d_in[1];
    const float* W_dyn     = (const float*)d_in[2];
    const float* b_dyn     = (const float*)d_in[3];
    const int*   t_idx     = (const int*)d_in[4];
    float* out = (float*)d_out;

    void* fn = nullptr;
    cudaDriverEntryPointQueryResult qr;
    cudaGetDriverEntryPoint("cuTensorMapEncodeTiled", &fn, cudaEnableDefault, &qr);
    EncodeTiledFn encode = (EncodeTiledFn)fn;

    void* zaddr = nullptr;  cudaGetSymbolAddress(&zaddr, g_zctx);
    void* zgaddr = nullptr; cudaGetSymbolAddress(&zgaddr, g_zgT);

    CUtensorMap tmW, tmZ, tmA, tmB;
    make_map2d(encode, &tmW, (void*)W_dyn,     KDIM, NOUT, 32, 256);
    make_map2d(encode, &tmZ, zaddr,            KDIM, TT,   32, 16);
    make_map2d(encode, &tmA, (void*)relations, K1,   M1,   32, 64);
    make_map2d(encode, &tmB, zgaddr,           K1,   NCOL, 32, 64);

    cudaFuncSetAttribute(mlp_kernel,   cudaFuncAttributeMaxDynamicSharedMemorySize, SMEM_BYTES);
    cudaFuncSetAttribute(gemm1_kernel, cudaFuncAttributeMaxDynamicSharedMemorySize, G1_SMEM);

    gather_kernel<<<625, 256>>>(factors, t_idx);
    dim3 g1(63, G1KB);
    gemm1_kernel<<<g1, 256, G1_SMEM>>>(tmA, tmB);
    merge_kernel<<<(M1 * 64 + 255) / 256, 256>>>();
    dim3 grid(16, KSPLIT);      // 16 row-blocks x 9 k-splits = 144 blocks, 1/SM
    mlp_kernel<<<grid, 256, SMEM_BYTES>>>(tmW, tmZ);
    epilogue_kernel<<<(NOUT * 4 + 255) / 256, 256>>>(b_dyn, out);
}